// round 1
// baseline (speedup 1.0000x reference)
#include <cuda_runtime.h>
#include <math.h>

#define B_ 32768
#define F_ 512
#define H_ 256
#define C_ 100
#define E_ 8

// Scratch (static device globals — no allocations allowed)
__device__ float g_h[(size_t)E_ * B_ * H_];        // 256 MB: relu(x@W1+b1) per expert
__device__ float g_preds[(size_t)E_ * B_ * C_];    // fallback preds if out buffer is combined-only
__device__ int   g_top2[B_];
__device__ int   g_counts[E_];

// ---------------------------------------------------------------------------
// Gating: logits = x @ Wg ; top-2 (softmax monotonic -> same indices)
// One warp per row. Wg (512x8) staged in smem with stride-9 padding.
// ---------------------------------------------------------------------------
__global__ __launch_bounds__(256) void gate_kernel(const float* __restrict__ x,
                                                   const float* __restrict__ Wg) {
    __shared__ float wgs[F_ * 9];
    __shared__ int cnt[E_];
    const int tid = threadIdx.x;
    if (tid < E_) cnt[tid] = 0;
    for (int i = tid; i < F_ * E_; i += 256) {
        int f = i >> 3, e = i & 7;
        wgs[f * 9 + e] = Wg[i];
    }
    __syncthreads();

    const int warp = tid >> 5, lane = tid & 31;
    const int row = blockIdx.x * 8 + warp;
    const float* xr = x + (size_t)row * F_;

    float acc[E_];
#pragma unroll
    for (int e = 0; e < E_; e++) acc[e] = 0.f;
#pragma unroll
    for (int i = 0; i < F_ / 32; i++) {
        int f = i * 32 + lane;
        float xv = xr[f];
#pragma unroll
        for (int e = 0; e < E_; e++) acc[e] += xv * wgs[f * 9 + e];
    }
#pragma unroll
    for (int off = 16; off; off >>= 1)
#pragma unroll
        for (int e = 0; e < E_; e++)
            acc[e] += __shfl_xor_sync(0xffffffffu, acc[e], off);

    if (lane == 0) {
        int i1 = 0;
#pragma unroll
        for (int e = 1; e < E_; e++) if (acc[e] > acc[i1]) i1 = e;   // strict > : earliest index on tie
        int i2 = (i1 == 0) ? 1 : 0;
#pragma unroll
        for (int e = 0; e < E_; e++) if (e != i1 && acc[e] > acc[i2]) i2 = e;
        g_top2[row] = i1 | (i2 << 8);
        atomicAdd(&cnt[i1], 1);
        atomicAdd(&cnt[i2], 1);
    }
    __syncthreads();
    if (tid < E_ && cnt[tid]) atomicAdd(&g_counts[tid], cnt[tid]);
}

// ---------------------------------------------------------------------------
// GEMM1: g_h[e] = relu(x[B,F] @ W1[e][F,H] + b1[e])
// 128x128x16 tile, 256 threads, 8x8 microtile, double-buffered smem.
// Grid: (H/128, B/128, E)
// ---------------------------------------------------------------------------
__global__ __launch_bounds__(256, 2)
void gemm1_kernel(const float* __restrict__ X, const float* __restrict__ W1,
                  const float* __restrict__ b1) {
    __shared__ float As[2][16][128];   // As[k][m]
    __shared__ float Bs[2][16][128];   // Bs[k][n]

    const int e  = blockIdx.z;
    const int n0 = blockIdx.x * 128;
    const int m0 = blockIdx.y * 128;
    const float* Bsrc = W1 + (size_t)e * (F_ * H_);
    const int tid = threadIdx.x;

    // A loader: thread -> row m = tid>>1, 8 consecutive k at (tid&1)*8
    const int a_m = tid >> 1;
    const int a_k = (tid & 1) * 8;
    const float* aPtr = X + (size_t)(m0 + a_m) * F_ + a_k;
    // B loader: thread -> k row tid>>4, 8 consecutive n at (tid&15)*8
    const int b_k = tid >> 4;
    const int b_n = (tid & 15) * 8;
    const float* bPtr = Bsrc + (size_t)b_k * H_ + n0 + b_n;

    float4 aR0, aR1, bR0, bR1;
    aR0 = *(const float4*)(aPtr);
    aR1 = *(const float4*)(aPtr + 4);
    bR0 = *(const float4*)(bPtr);
    bR1 = *(const float4*)(bPtr + 4);
    As[0][a_k + 0][a_m] = aR0.x; As[0][a_k + 1][a_m] = aR0.y;
    As[0][a_k + 2][a_m] = aR0.z; As[0][a_k + 3][a_m] = aR0.w;
    As[0][a_k + 4][a_m] = aR1.x; As[0][a_k + 5][a_m] = aR1.y;
    As[0][a_k + 6][a_m] = aR1.z; As[0][a_k + 7][a_m] = aR1.w;
    *(float4*)&Bs[0][b_k][b_n]     = bR0;
    *(float4*)&Bs[0][b_k][b_n + 4] = bR1;
    __syncthreads();

    const int tx = (tid & 15) * 8;   // n offset
    const int ty = (tid >> 4) * 8;   // m offset
    float acc[8][8];
#pragma unroll
    for (int i = 0; i < 8; i++)
#pragma unroll
        for (int j = 0; j < 8; j++) acc[i][j] = 0.f;

    const int NT = F_ / 16;  // 32
    for (int t = 0; t < NT; t++) {
        const int buf = t & 1;
        if (t + 1 < NT) {
            const float* ap = aPtr + (t + 1) * 16;
            aR0 = *(const float4*)(ap);
            aR1 = *(const float4*)(ap + 4);
            const float* bp = bPtr + (size_t)(t + 1) * 16 * H_;
            bR0 = *(const float4*)(bp);
            bR1 = *(const float4*)(bp + 4);
        }
#pragma unroll
        for (int k = 0; k < 16; k++) {
            float4 a0 = *(const float4*)&As[buf][k][ty];
            float4 a1 = *(const float4*)&As[buf][k][ty + 4];
            float4 b0 = *(const float4*)&Bs[buf][k][tx];
            float4 b1 = *(const float4*)&Bs[buf][k][tx + 4];
            float av[8] = {a0.x, a0.y, a0.z, a0.w, a1.x, a1.y, a1.z, a1.w};
            float bv[8] = {b0.x, b0.y, b0.z, b0.w, b1.x, b1.y, b1.z, b1.w};
#pragma unroll
            for (int i = 0; i < 8; i++)
#pragma unroll
                for (int j = 0; j < 8; j++) acc[i][j] += av[i] * bv[j];
        }
        if (t + 1 < NT) {
            const int nb = buf ^ 1;
            As[nb][a_k + 0][a_m] = aR0.x; As[nb][a_k + 1][a_m] = aR0.y;
            As[nb][a_k + 2][a_m] = aR0.z; As[nb][a_k + 3][a_m] = aR0.w;
            As[nb][a_k + 4][a_m] = aR1.x; As[nb][a_k + 5][a_m] = aR1.y;
            As[nb][a_k + 6][a_m] = aR1.z; As[nb][a_k + 7][a_m] = aR1.w;
            *(float4*)&Bs[nb][b_k][b_n]     = bR0;
            *(float4*)&Bs[nb][b_k][b_n + 4] = bR1;
            __syncthreads();
        }
    }

    // epilogue: + bias, relu, store to g_h
    float bias[8];
    *(float4*)&bias[0] = *(const float4*)(b1 + e * H_ + n0 + tx);
    *(float4*)&bias[4] = *(const float4*)(b1 + e * H_ + n0 + tx + 4);
    float* outp = g_h + ((size_t)e * B_ + m0 + ty) * H_ + n0 + tx;
#pragma unroll
    for (int i = 0; i < 8; i++) {
        float4 o0, o1;
        o0.x = fmaxf(acc[i][0] + bias[0], 0.f);
        o0.y = fmaxf(acc[i][1] + bias[1], 0.f);
        o0.z = fmaxf(acc[i][2] + bias[2], 0.f);
        o0.w = fmaxf(acc[i][3] + bias[3], 0.f);
        o1.x = fmaxf(acc[i][4] + bias[4], 0.f);
        o1.y = fmaxf(acc[i][5] + bias[5], 0.f);
        o1.z = fmaxf(acc[i][6] + bias[6], 0.f);
        o1.w = fmaxf(acc[i][7] + bias[7], 0.f);
        *(float4*)(outp + (size_t)i * H_)     = o0;
        *(float4*)(outp + (size_t)i * H_ + 4) = o1;
    }
}

// ---------------------------------------------------------------------------
// GEMM2: preds[e] = g_h[e][B,H] @ W2[e][H,C] + b2[e]
// Block: 128 rows x all 100 cols (padded to 112). Thread: 8 rows x 7 cols.
// Grid: (B/128, E)
// ---------------------------------------------------------------------------
__global__ __launch_bounds__(256)
void gemm2_kernel(const float* __restrict__ W2, const float* __restrict__ b2,
                  float* __restrict__ preds_arg) {
    __shared__ float As[16][128];   // As[k][m]
    __shared__ float Bs[16][112];   // Bs[k][c]

    float* preds = preds_arg ? preds_arg : g_preds;
    const int e  = blockIdx.y;
    const int m0 = blockIdx.x * 128;
    const float* Asrc = g_h + (size_t)e * B_ * H_;
    const float* Bsrc = W2 + (size_t)e * H_ * C_;
    const int tid = threadIdx.x;

    const int a_m = tid >> 1;
    const int a_k = (tid & 1) * 8;
    const float* aPtr = Asrc + (size_t)(m0 + a_m) * H_ + a_k;

    const int tx = (tid & 15) * 7;   // col offset (0..105)
    const int ty = (tid >> 4) * 8;   // row offset
    float acc[8][7];
#pragma unroll
    for (int i = 0; i < 8; i++)
#pragma unroll
        for (int j = 0; j < 7; j++) acc[i][j] = 0.f;

    for (int t = 0; t < H_ / 16; t++) {
        float4 aR0 = *(const float4*)(aPtr + t * 16);
        float4 aR1 = *(const float4*)(aPtr + t * 16 + 4);
        As[a_k + 0][a_m] = aR0.x; As[a_k + 1][a_m] = aR0.y;
        As[a_k + 2][a_m] = aR0.z; As[a_k + 3][a_m] = aR0.w;
        As[a_k + 4][a_m] = aR1.x; As[a_k + 5][a_m] = aR1.y;
        As[a_k + 6][a_m] = aR1.z; As[a_k + 7][a_m] = aR1.w;
        for (int i = tid; i < 16 * C_; i += 256) {
            int kk = i / C_, cc = i - kk * C_;
            Bs[kk][cc] = Bsrc[(size_t)(t * 16 + kk) * C_ + cc];
        }
        __syncthreads();
#pragma unroll
        for (int k = 0; k < 16; k++) {
            float4 a0 = *(const float4*)&As[k][ty];
            float4 a1 = *(const float4*)&As[k][ty + 4];
            float av[8] = {a0.x, a0.y, a0.z, a0.w, a1.x, a1.y, a1.z, a1.w};
            float bv[7];
#pragma unroll
            for (int j = 0; j < 7; j++) bv[j] = Bs[k][tx + j];
#pragma unroll
            for (int i = 0; i < 8; i++)
#pragma unroll
                for (int j = 0; j < 7; j++) acc[i][j] += av[i] * bv[j];
        }
        __syncthreads();
    }

#pragma unroll
    for (int j = 0; j < 7; j++) {
        int c = tx + j;
        if (c < C_) {
            float bias = b2[e * C_ + c];
#pragma unroll
            for (int i = 0; i < 8; i++)
                preds[((size_t)e * B_ + m0 + ty + i) * C_ + c] = acc[i][j] + bias;
        }
    }
}

// ---------------------------------------------------------------------------
// Combine: combined[b] = 0.5*(softmax(preds[e1,b]) + softmax(preds[e2,b]))
// One warp per row; lane handles cols {lane, lane+32, lane+64, lane+96}.
// ---------------------------------------------------------------------------
__global__ __launch_bounds__(256)
void combine_kernel(const float* __restrict__ preds_arg, float* __restrict__ combined) {
    const float* preds = preds_arg ? preds_arg : g_preds;
    const int warp = threadIdx.x >> 5, lane = threadIdx.x & 31;
    const int row = blockIdx.x * 8 + warp;
    const int packed = g_top2[row];
    const int e1 = packed & 0xFF, e2 = (packed >> 8) & 0xFF;
    const float* p1 = preds + ((size_t)e1 * B_ + row) * C_;
    const float* p2 = preds + ((size_t)e2 * B_ + row) * C_;

    float v1[4], v2[4];
#pragma unroll
    for (int i = 0; i < 4; i++) {
        int c = lane + i * 32;
        bool ok = c < C_;
        v1[i] = ok ? p1[c] : -3.4e38f;
        v2[i] = ok ? p2[c] : -3.4e38f;
    }
    float m1 = fmaxf(fmaxf(v1[0], v1[1]), fmaxf(v1[2], v1[3]));
    float m2 = fmaxf(fmaxf(v2[0], v2[1]), fmaxf(v2[2], v2[3]));
#pragma unroll
    for (int off = 16; off; off >>= 1) {
        m1 = fmaxf(m1, __shfl_xor_sync(0xffffffffu, m1, off));
        m2 = fmaxf(m2, __shfl_xor_sync(0xffffffffu, m2, off));
    }
    float s1 = 0.f, s2 = 0.f;
#pragma unroll
    for (int i = 0; i < 4; i++) {
        int c = lane + i * 32;
        v1[i] = (c < C_) ? expf(v1[i] - m1) : 0.f;
        v2[i] = (c < C_) ? expf(v2[i] - m2) : 0.f;
        s1 += v1[i];
        s2 += v2[i];
    }
#pragma unroll
    for (int off = 16; off; off >>= 1) {
        s1 += __shfl_xor_sync(0xffffffffu, s1, off);
        s2 += __shfl_xor_sync(0xffffffffu, s2, off);
    }
    const float r1 = 0.5f / s1, r2 = 0.5f / s2;
    float* outr = combined + (size_t)row * C_;
#pragma unroll
    for (int i = 0; i < 4; i++) {
        int c = lane + i * 32;
        if (c < C_) outr[c] = v1[i] * r1 + v2[i] * r2;
    }
}

__global__ void zero_counts_kernel() {
    if (threadIdx.x < E_) g_counts[threadIdx.x] = 0;
}
__global__ void write_counts_kernel(float* __restrict__ dst) {
    if (threadIdx.x < E_) dst[threadIdx.x] = (float)g_counts[threadIdx.x];
}

// ---------------------------------------------------------------------------
extern "C" void kernel_launch(void* const* d_in, const int* in_sizes, int n_in,
                              void* d_out, int out_size) {
    const float* x  = (const float*)d_in[0];
    const float* W1 = (const float*)d_in[1];
    const float* b1 = (const float*)d_in[2];
    const float* W2 = (const float*)d_in[3];
    const float* b2 = (const float*)d_in[4];
    const float* Wg = (const float*)d_in[5];
    float* out = (float*)d_out;

    const size_t n_combined = (size_t)B_ * C_;            // 3,276,800
    const size_t n_preds    = (size_t)E_ * B_ * C_;       // 26,214,400
    const bool has_preds  = (size_t)out_size >= n_combined + n_preds;
    const bool has_counts = (size_t)out_size >= n_combined + n_preds + E_;

    float* combined  = out;
    float* preds_out = has_preds ? out + n_combined : nullptr;  // nullptr -> g_preds fallback

    zero_counts_kernel<<<1, 32>>>();
    gate_kernel<<<B_ / 8, 256>>>(x, Wg);

    dim3 g1(H_ / 128, B_ / 128, E_);
    gemm1_kernel<<<g1, 256>>>(x, W1, b1);

    dim3 g2(B_ / 128, E_);
    gemm2_kernel<<<g2, 256>>>(W2, b2, preds_out);

    combine_kernel<<<B_ / 8, 256>>>(preds_out, combined);

    if (has_counts) write_counts_kernel<<<1, 32>>>(out + n_combined + n_preds);
}